// round 2
// baseline (speedup 1.0000x reference)
#include <cuda_runtime.h>

#define B_   16
#define CIN  256
#define COUT 256
#define HH   64
#define WW   64
#define MID  64
#define HW   (HH*WW)            // 4096
#define WELEM (COUT*CIN*9)      // 589824

#define CI_T 8
#define XP   74                 // swizzled pitch for 66 cols
#define WP   66                 // padded pitch for 64 o (conflict-free STS, 8B-aligned rows)

typedef unsigned long long ull;

// ---------------- device scratch (static allocation only) ----------------
__device__ float g_pooled[B_*CIN];
__device__ float g_bsoft[B_*4*4];           // [b][branch][4]
__device__ float g_alpha[B_*4];             // [b][4]
__device__ float g_dynw[(size_t)B_*WELEM];  // 37.7 MB per-sample kernels
__device__ float g_scale[COUT];
__device__ float g_shift[COUT];

// ---------------- packed f32x2 helpers ----------------
__device__ __forceinline__ ull pk2(float lo, float hi){
    ull r; asm("mov.b64 %0, {%1,%2};" : "=l"(r) : "f"(lo), "f"(hi)); return r;
}
__device__ __forceinline__ void upk2(ull v, float& lo, float& hi){
    asm("mov.b64 {%0,%1}, %2;" : "=f"(lo), "=f"(hi) : "l"(v));
}
__device__ __forceinline__ void ffma2(ull& d, ull a, ull b){
    asm("fma.rn.f32x2 %0, %1, %2, %0;" : "+l"(d) : "l"(a), "l"(b));
}

// ---------------- K1: global average pool ----------------
__global__ void pool_kernel(const float* __restrict__ x){
    int bc = blockIdx.x;                       // b*CIN + c
    const float* p = x + (size_t)bc * HW;
    float s = 0.f;
    for (int i = threadIdx.x; i < HW; i += 256) s += p[i];
    __shared__ float red[8];
    for (int o = 16; o; o >>= 1) s += __shfl_down_sync(0xffffffffu, s, o);
    if ((threadIdx.x & 31) == 0) red[threadIdx.x >> 5] = s;
    __syncthreads();
    if (threadIdx.x < 8){
        s = red[threadIdx.x];
        for (int o = 4; o; o >>= 1) s += __shfl_down_sync(0x000000ffu, s, o);
        if (threadIdx.x == 0) g_pooled[bc] = s * (1.f/(float)HW);
    }
}

// ---------------- K2: one attention branch (Linear-ReLU-Linear-softmax) ----------------
__global__ void branch_kernel(const float* __restrict__ w1_0, const float* __restrict__ w2_0, const float* __restrict__ b2_0,
                              const float* __restrict__ w1_1, const float* __restrict__ w2_1, const float* __restrict__ b2_1,
                              const float* __restrict__ w1_2, const float* __restrict__ w2_2, const float* __restrict__ b2_2,
                              const float* __restrict__ w1_3, const float* __restrict__ w2_3, const float* __restrict__ b2_3){
    int n = blockIdx.x;          // branch
    int b = blockIdx.y;          // sample
    const float* w1 = (n==0)?w1_0:(n==1)?w1_1:(n==2)?w1_2:w1_3;
    const float* w2 = (n==0)?w2_0:(n==1)?w2_1:(n==2)?w2_2:w2_3;
    const float* b2 = (n==0)?b2_0:(n==1)?b2_1:(n==2)?b2_2:b2_3;

    __shared__ float pl[CIN];
    __shared__ float h[MID];
    __shared__ float logit[4];
    int t = threadIdx.x;         // 64 threads
    for (int i = t; i < CIN; i += 64) pl[i] = g_pooled[b*CIN + i];
    __syncthreads();
    float acc = 0.f;
    const float* w1r = w1 + t*CIN;
    for (int k = 0; k < CIN; ++k) acc += pl[k] * w1r[k];
    h[t] = fmaxf(acc, 0.f);
    __syncthreads();
    if (t < 4){
        float a = b2[t];
        const float* w2r = w2 + t*MID;
        for (int k = 0; k < MID; ++k) a += h[k] * w2r[k];
        logit[t] = a;
    }
    __syncthreads();
    if (t == 0){
        float m = fmaxf(fmaxf(logit[0],logit[1]), fmaxf(logit[2],logit[3]));
        float e0 = expf(logit[0]-m), e1 = expf(logit[1]-m);
        float e2 = expf(logit[2]-m), e3 = expf(logit[3]-m);
        float inv = 1.f/(e0+e1+e2+e3);
        float* dst = &g_bsoft[(b*4 + n)*4];
        dst[0]=e0*inv; dst[1]=e1*inv; dst[2]=e2*inv; dst[3]=e3*inv;
    }
}

// ---------------- K2b: alpha = product of branch softmaxes ----------------
__global__ void alpha_kernel(){
    int i = threadIdx.x;
    if (i < B_*4){
        int b = i >> 2, j = i & 3;
        g_alpha[i] = g_bsoft[(b*4+0)*4+j] * g_bsoft[(b*4+1)*4+j]
                   * g_bsoft[(b*4+2)*4+j] * g_bsoft[(b*4+3)*4+j];
    }
}

// ---------------- K3: combine 4 weight banks into per-sample kernels ----------------
__global__ void combine_kernel(const float* __restrict__ wbank){
    __shared__ float al[B_*4];
    if (threadIdx.x < B_*4) al[threadIdx.x] = g_alpha[threadIdx.x];
    __syncthreads();
    int pos = blockIdx.x*256 + threadIdx.x;   // < WELEM
    float w0 = wbank[pos];
    float w1 = wbank[(size_t)WELEM   + pos];
    float w2 = wbank[(size_t)WELEM*2 + pos];
    float w3 = wbank[(size_t)WELEM*3 + pos];
    #pragma unroll
    for (int b = 0; b < B_; ++b){
        float v = al[b*4+0]*w0 + al[b*4+1]*w1 + al[b*4+2]*w2 + al[b*4+3]*w3;
        g_dynw[(size_t)b*WELEM + pos] = v;
    }
}

// ---------------- K4: per-sample dynamic 3x3 conv (implicit GEMM, FFMA2) ----------------
// grid: (COUT/64, HH/2, B_). block: 256 threads.
// block tile: 64 out-channels x (2 rows x 64 cols). micro-tile: 4o x 8s, f32x2 paired over o.
__global__ void __launch_bounds__(256)
conv_kernel(const float* __restrict__ x, float* __restrict__ out){
    __shared__ float Xs[CI_T*4*XP];   // x slab: [ci][4 rows][66 cols swizzled]
    __shared__ float Ws[CI_T*9*WP];   // weights: [ci*9+tap][64 o + pad]

    const int tid  = threadIdx.x;
    const int oBlk = blockIdx.x;          // 0..3
    const int h0   = blockIdx.y * 2;      // output row pair
    const int b    = blockIdx.z;

    const int g   = tid & 15;             // spatial group
    const int row = g >> 3;               // 0/1
    const int cg  = g & 7;                // column group: s0 = 8*cg
    const int o0  = (tid >> 4) * 4;       // 4 out-channels per thread

    ull acc0[8], acc1[8];
    #pragma unroll
    for (int s = 0; s < 8; ++s){ acc0[s] = 0ull; acc1[s] = 0ull; }

    const float* dynw_b = g_dynw + (((size_t)b*COUT + oBlk*64)*CIN)*9;

    for (int ci0 = 0; ci0 < CIN; ci0 += CI_T){
        __syncthreads();
        // --- load x slab: CI_T channels x 4 rows x 66 cols (zero-padded), swizzled ---
        for (int idx = tid; idx < CI_T*4*66; idx += 256){
            int ci  = idx / (4*66);
            int rem = idx - ci*(4*66);
            int r   = rem / 66;
            int col = rem - r*66;
            int gy = h0 - 1 + r;
            int gx = col - 1;
            float v = 0.f;
            if ((unsigned)gy < (unsigned)HH && (unsigned)gx < (unsigned)WW)
                v = x[(((size_t)b*CIN + ci0 + ci)*HH + gy)*WW + gx];
            Xs[(ci*4 + r)*XP + col + (col>>3)] = v;
        }
        // --- load weights: 64 o x CI_T ci x 9 taps -> [ci*9+tap][o] (pitch 66) ---
        const float* wsrc = dynw_b + (size_t)ci0*9;
        for (int idx = tid; idx < CI_T*9*64; idx += 256){
            int o = idx / (CI_T*9);
            int r = idx - o*(CI_T*9);          // ci*9+tap
            Ws[r*WP + o] = wsrc[(size_t)o*(CIN*9) + r];
        }
        __syncthreads();

        #pragma unroll 1
        for (int ci = 0; ci < CI_T; ++ci){
            const float* xbase = Xs + (ci*4 + row)*XP + 9*cg;
            const float* wbase = Ws + ci*9*WP + o0;
            #pragma unroll
            for (int dy = 0; dy < 3; ++dy){
                const float* xr = xbase + dy*XP;
                ull xd[10];
                #pragma unroll
                for (int j = 0; j < 10; ++j){
                    float v = xr[j + (j>>3)];      // swizzle: +1 past col 7 boundary
                    xd[j] = pk2(v, v);
                }
                #pragma unroll
                for (int dx = 0; dx < 3; ++dx){
                    const float* wr = wbase + (dy*3+dx)*WP;
                    ull w01 = *(const ull*)(wr);
                    ull w23 = *(const ull*)(wr + 2);
                    #pragma unroll
                    for (int s = 0; s < 8; ++s){
                        ffma2(acc0[s], w01, xd[s+dx]);
                        ffma2(acc1[s], w23, xd[s+dx]);
                    }
                }
            }
        }
    }

    // --- epilogue: unpack and store (float4-coalesced) ---
    const int h = h0 + row;
    float v[4][8];
    #pragma unroll
    for (int s = 0; s < 8; ++s){
        upk2(acc0[s], v[0][s], v[1][s]);
        upk2(acc1[s], v[2][s], v[3][s]);
    }
    #pragma unroll
    for (int k = 0; k < 4; ++k){
        float* po = out + (((size_t)b*COUT + oBlk*64 + o0 + k)*HH + h)*WW + 8*cg;
        ((float4*)po)[0] = make_float4(v[k][0], v[k][1], v[k][2], v[k][3]);
        ((float4*)po)[1] = make_float4(v[k][4], v[k][5], v[k][6], v[k][7]);
    }
}

// ---------------- K5: BN batch statistics (one block per channel) ----------------
__global__ void stats_kernel(const float* __restrict__ out,
                             const float* __restrict__ gamma,
                             const float* __restrict__ beta){
    int c = blockIdx.x;
    float s = 0.f, sq = 0.f;
    for (int b = 0; b < B_; ++b){
        const float* p = out + ((size_t)b*COUT + c)*HW;
        for (int i = threadIdx.x; i < HW; i += 256){
            float vv = p[i]; s += vv; sq += vv*vv;
        }
    }
    __shared__ float r1[8], r2[8];
    for (int o = 16; o; o >>= 1){
        s  += __shfl_down_sync(0xffffffffu, s,  o);
        sq += __shfl_down_sync(0xffffffffu, sq, o);
    }
    if ((threadIdx.x & 31) == 0){ r1[threadIdx.x>>5] = s; r2[threadIdx.x>>5] = sq; }
    __syncthreads();
    if (threadIdx.x < 8){
        s = r1[threadIdx.x]; sq = r2[threadIdx.x];
        for (int o = 4; o; o >>= 1){
            s  += __shfl_down_sync(0x000000ffu, s,  o);
            sq += __shfl_down_sync(0x000000ffu, sq, o);
        }
        if (threadIdx.x == 0){
            const float invN = 1.f/(float)(B_*HW);
            float mean = s * invN;
            float var  = sq * invN - mean*mean;
            float rstd = rsqrtf(var + 1e-5f);
            float sc = rstd * gamma[c];
            g_scale[c] = sc;
            g_shift[c] = beta[c] - mean*sc;
        }
    }
}

// ---------------- K6: normalize in place ----------------
__global__ void norm_kernel(float* __restrict__ out){
    size_t i = (size_t)blockIdx.x*256 + threadIdx.x;   // float4 index
    int c = (int)((i >> 10) & (COUT-1));               // 1024 float4 per (b,c) plane
    float sc = g_scale[c], sh = g_shift[c];
    float4* p = (float4*)out;
    float4 vv = p[i];
    vv.x = vv.x*sc + sh; vv.y = vv.y*sc + sh;
    vv.z = vv.z*sc + sh; vv.w = vv.w*sc + sh;
    p[i] = vv;
}

// ---------------- launch ----------------
extern "C" void kernel_launch(void* const* d_in, const int* in_sizes, int n_in,
                              void* d_out, int out_size){
    const float* x     = (const float*)d_in[0];
    const float* wbank = (const float*)d_in[1];
    const float* gamma = (const float*)d_in[2];
    const float* beta  = (const float*)d_in[3];
    const float* w1s = (const float*)d_in[4];
    const float* w2s = (const float*)d_in[5];
    const float* b2s = (const float*)d_in[6];
    const float* w1c = (const float*)d_in[7];
    const float* w2c = (const float*)d_in[8];
    const float* b2c = (const float*)d_in[9];
    const float* w1f = (const float*)d_in[10];
    const float* w2f = (const float*)d_in[11];
    const float* b2f = (const float*)d_in[12];
    const float* w1w = (const float*)d_in[13];
    const float* w2w = (const float*)d_in[14];
    const float* b2w = (const float*)d_in[15];
    float* out = (float*)d_out;

    pool_kernel<<<B_*CIN, 256>>>(x);
    branch_kernel<<<dim3(4, B_), 64>>>(w1s,w2s,b2s, w1c,w2c,b2c, w1f,w2f,b2f, w1w,w2w,b2w);
    alpha_kernel<<<1, 64>>>();
    combine_kernel<<<WELEM/256, 256>>>(wbank);
    conv_kernel<<<dim3(COUT/64, HH/2, B_), 256>>>(x, out);
    stats_kernel<<<COUT, 256>>>(out, gamma, beta);
    norm_kernel<<<(B_*COUT*HW/4 + 255)/256, 256>>>(out);
}

// round 4
// speedup vs baseline: 2.1862x; 2.1862x over previous
#include <cuda_runtime.h>
#include <cstdint>

#define B_   16
#define CIN  256
#define COUT 256
#define HH   64
#define WW   64
#define MID  64
#define HW   4096
#define WELEM (COUT*CIN*9)

// conv tiling
#define SP       66                 // slab col pitch (floats)
#define CISTRIDE (4*SP)             // 264 floats per ci
#define SLAB_F   (32*CISTRIDE)      // 8448 floats
#define WPITCH   136                // B panel row pitch (floats)
#define PANEL_F  (32*WPITCH)        // 4352 floats
#define PANEL_B  (PANEL_F*4)        // 17408 bytes
#define NBUF     4
#define CONV_SMEM (NBUF*PANEL_B + SLAB_F*4)   // 69632 + 33792 = 103424

// ---------------- device scratch ----------------
__device__ float g_pooled[B_*CIN];
__device__ float g_bsoft[B_*16];
__device__ float g_alpha[B_*4];
__device__ __align__(1024) float g_wfmt[(size_t)B_*2*72*PANEL_F];  // ~40 MB tf32 panels
__device__ float g_scale[COUT];
__device__ float g_shift[COUT];

// ---------------- helpers ----------------
__device__ __forceinline__ uint32_t smem_u32(const void* p){
    uint32_t a; asm("{ .reg .u64 t; cvta.to.shared.u64 t, %1; cvt.u32.u64 %0, t; }" : "=r"(a) : "l"(p)); return a;
}
__device__ __forceinline__ uint32_t cvt_tf32(float f){
    uint32_t u; asm("cvt.rna.tf32.f32 %0, %1;" : "=r"(u) : "f"(f)); return u;
}
__device__ __forceinline__ uint32_t lds32(uint32_t a){
    uint32_t v; asm("ld.shared.b32 %0, [%1];" : "=r"(v) : "r"(a)); return v;
}
__device__ __forceinline__ void mma_tf32(float* d, const uint32_t* a, uint32_t b0, uint32_t b1){
    asm("mma.sync.aligned.m16n8k8.row.col.f32.tf32.tf32.f32 "
        "{%0,%1,%2,%3}, {%4,%5,%6,%7}, {%8,%9}, {%0,%1,%2,%3};"
        : "+f"(d[0]), "+f"(d[1]), "+f"(d[2]), "+f"(d[3])
        : "r"(a[0]), "r"(a[1]), "r"(a[2]), "r"(a[3]), "r"(b0), "r"(b1));
}
__device__ __forceinline__ void cp16(uint32_t dst, const float* src){
    asm volatile("cp.async.cg.shared.global [%0], [%1], 16;" :: "r"(dst), "l"(src) : "memory");
}
__device__ __forceinline__ void cp_commit(){ asm volatile("cp.async.commit_group;" ::: "memory"); }
__device__ __forceinline__ void cp_wait2(){ asm volatile("cp.async.wait_group 2;" ::: "memory"); }

// ---------------- K1: GAP ----------------
__global__ void pool_kernel(const float* __restrict__ x){
    int bc = blockIdx.x;
    const float* p = x + (size_t)bc * HW;
    float s = 0.f;
    for (int i = threadIdx.x; i < HW; i += 256) s += p[i];
    __shared__ float red[8];
    for (int o = 16; o; o >>= 1) s += __shfl_down_sync(0xffffffffu, s, o);
    if ((threadIdx.x & 31) == 0) red[threadIdx.x >> 5] = s;
    __syncthreads();
    if (threadIdx.x < 8){
        s = red[threadIdx.x];
        for (int o = 4; o; o >>= 1) s += __shfl_down_sync(0x000000ffu, s, o);
        if (threadIdx.x == 0) g_pooled[bc] = s * (1.f/(float)HW);
    }
}

// ---------------- K2: attention branches ----------------
__global__ void branch_kernel(const float* __restrict__ w1_0, const float* __restrict__ w2_0, const float* __restrict__ b2_0,
                              const float* __restrict__ w1_1, const float* __restrict__ w2_1, const float* __restrict__ b2_1,
                              const float* __restrict__ w1_2, const float* __restrict__ w2_2, const float* __restrict__ b2_2,
                              const float* __restrict__ w1_3, const float* __restrict__ w2_3, const float* __restrict__ b2_3){
    int n = blockIdx.x, b = blockIdx.y;
    const float* w1 = (n==0)?w1_0:(n==1)?w1_1:(n==2)?w1_2:w1_3;
    const float* w2 = (n==0)?w2_0:(n==1)?w2_1:(n==2)?w2_2:w2_3;
    const float* b2 = (n==0)?b2_0:(n==1)?b2_1:(n==2)?b2_2:b2_3;
    __shared__ float pl[CIN]; __shared__ float h[MID]; __shared__ float logit[4];
    int t = threadIdx.x;
    for (int i = t; i < CIN; i += 64) pl[i] = g_pooled[b*CIN + i];
    __syncthreads();
    float acc = 0.f;
    const float* w1r = w1 + t*CIN;
    for (int k = 0; k < CIN; ++k) acc += pl[k] * w1r[k];
    h[t] = fmaxf(acc, 0.f);
    __syncthreads();
    if (t < 4){
        float a = b2[t];
        const float* w2r = w2 + t*MID;
        for (int k = 0; k < MID; ++k) a += h[k] * w2r[k];
        logit[t] = a;
    }
    __syncthreads();
    if (t == 0){
        float m = fmaxf(fmaxf(logit[0],logit[1]), fmaxf(logit[2],logit[3]));
        float e0 = expf(logit[0]-m), e1 = expf(logit[1]-m);
        float e2 = expf(logit[2]-m), e3 = expf(logit[3]-m);
        float inv = 1.f/(e0+e1+e2+e3);
        float* dst = &g_bsoft[(b*4 + n)*4];
        dst[0]=e0*inv; dst[1]=e1*inv; dst[2]=e2*inv; dst[3]=e3*inv;
    }
}

__global__ void alpha_kernel(){
    int i = threadIdx.x;
    if (i < B_*4){
        int b = i >> 2, j = i & 3;
        g_alpha[i] = g_bsoft[(b*4+0)*4+j] * g_bsoft[(b*4+1)*4+j]
                   * g_bsoft[(b*4+2)*4+j] * g_bsoft[(b*4+3)*4+j];
    }
}

// ---------------- K3: combine + format tf32 B panels ----------------
// grid 1024 = b(16) x oT(2) x cic(8) x ng(4); block 256.
// panel (cic*9+tap): [k=ci_local 0..31][n 0..127] pitch 136.
__global__ void combine_kernel(const float* __restrict__ wbank){
    int t = blockIdx.x;
    int ng = t & 3; t >>= 2;
    int cic = t & 7; t >>= 3;
    int oT = t & 1;
    int b  = t >> 1;
    __shared__ float al[4];
    __shared__ float tile[32*289];
    if (threadIdx.x < 4) al[threadIdx.x] = g_alpha[b*4 + threadIdx.x];
    __syncthreads();
    float a0 = al[0], a1 = al[1], a2 = al[2], a3 = al[3];

    // read phase: 32 n-rows x 288 (k,tap) contiguous floats each, coalesced
    for (int idx = threadIdx.x; idx < 32*288; idx += 256){
        int n = idx / 288, e = idx - n*288;       // e = k*9 + tap (source order)
        int k = e / 9, tap = e - k*9;
        size_t src = ((size_t)(oT*128 + ng*32 + n)*CIN + cic*32 + k)*9 + tap;
        float v = a0*wbank[src] + a1*wbank[(size_t)WELEM + src]
                + a2*wbank[(size_t)WELEM*2 + src] + a3*wbank[(size_t)WELEM*3 + src];
        tile[n*289 + tap*32 + k] = __uint_as_float(cvt_tf32(v));
    }
    __syncthreads();
    // write phase: coalesced 32-float chunks along n
    float* dbase = g_wfmt + (size_t)(b*2 + oT)*72*PANEL_F;
    for (int idx = threadIdx.x; idx < 32*288; idx += 256){
        int kt = idx >> 5, n = idx & 31;          // kt = tap*32 + k
        int tap = kt >> 5, k = kt & 31;
        dbase[(size_t)(cic*9 + tap)*PANEL_F + k*WPITCH + ng*32 + n] = tile[n*289 + kt];
    }
}

// ---------------- K4: tf32 mma.sync implicit-GEMM conv ----------------
// grid (2, 32, 16), 256 threads (8 warps, 2x4 warp grid), accum in regs.
__global__ void __launch_bounds__(256,1)
conv_kernel(const float* __restrict__ x, float* __restrict__ out){
    extern __shared__ float sm[];
    float* bpan = sm;                          // 4 x PANEL_F
    float* slab = sm + NBUF*PANEL_F;           // SLAB_F
    const int tid  = threadIdx.x;
    const int lane = tid & 31, wid = tid >> 5;
    const int wm = wid >> 2, wn = wid & 3;     // warp grid 2 x 4
    const int q = lane & 3, g = lane >> 2;     // quad / group
    const int oT = blockIdx.x, b = blockIdx.z;
    const int h0 = blockIdx.y * 2;

    const uint32_t slabU = smem_u32(slab);
    const uint32_t bU    = smem_u32(bpan);
    const float* wbase = g_wfmt + (size_t)(b*2 + oT)*72*PANEL_F;

    float acc[4][4][4];
    #pragma unroll
    for (int i = 0; i < 4; ++i)
        #pragma unroll
        for (int j = 0; j < 4; ++j)
            #pragma unroll
            for (int k = 0; k < 4; ++k) acc[i][j][k] = 0.f;

    // prologue: panels 0..2
    #pragma unroll
    for (int p = 0; p < 3; ++p){
        for (int i = tid; i < PANEL_F/4; i += 256)
            cp16(bU + (uint32_t)p*PANEL_B + i*16, wbase + (size_t)p*PANEL_F + i*4);
        cp_commit();
    }

    for (int c = 0; c < 8; ++c){
        #pragma unroll 1
        for (int t = 0; t < 9; ++t){
            const int p = c*9 + t;
            cp_wait2();                     // panel p resident
            __syncthreads();                // visible to all; buf (p-1)&3 free
            if (p + 3 < 72){
                const float* src = wbase + (size_t)(p+3)*PANEL_F;
                uint32_t dst = bU + (uint32_t)((p+3)&3)*PANEL_B;
                for (int i = tid; i < PANEL_F/4; i += 256)
                    cp16(dst + i*16, src + i*4);
            }
            cp_commit();                    // always commit (may be empty)

            if (t == 0){
                // stage x slab for chunk c (tf32-converted)
                for (int idx = tid; idx < SLAB_F; idx += 256){
                    int ci = idx / CISTRIDE;
                    int rem = idx - ci*CISTRIDE;
                    int r = rem / SP, col = rem - r*SP;
                    int gy = h0 - 1 + r, gx = col - 1;
                    float v = 0.f;
                    if (((unsigned)gy < 64u) & ((unsigned)gx < 64u))
                        v = x[(((size_t)b*CIN + c*32 + ci) << 12) + (gy << 6) + gx];
                    slab[idx] = __uint_as_float(cvt_tf32(v));
                }
                __syncthreads();
            }

            // consume tap t from buffer p&3
            const int dy = t / 3, dx = t - dy*3;
            const uint32_t bbuf = bU + (uint32_t)(p & 3)*PANEL_B;
            const uint32_t aBase = slabU + (uint32_t)(((q*4 + wm + dy)*SP) + (g + dx))*4;
            const uint32_t bBase = bbuf + (uint32_t)((q*WPITCH) + wn*32 + g)*4;

            #pragma unroll
            for (int kk = 0; kk < 4; ++kk){
                uint32_t A[4][4];
                const uint32_t a0 = aBase + (uint32_t)kk*8448;   // +8 ci
                #pragma unroll
                for (int mt = 0; mt < 4; ++mt){
                    uint32_t am = a0 + mt*64;
                    A[mt][0] = lds32(am);
                    A[mt][1] = lds32(am + 32);
                    A[mt][2] = lds32(am + 4224);        // ci+4
                    A[mt][3] = lds32(am + 4224 + 32);
                }
                const uint32_t br = bBase + (uint32_t)kk*8*WPITCH*4;
                #pragma unroll
                for (int nt = 0; nt < 4; ++nt){
                    uint32_t b0 = lds32(br + nt*32);
                    uint32_t b1 = lds32(br + nt*32 + 4*WPITCH*4);  // k+4
                    #pragma unroll
                    for (int mt = 0; mt < 4; ++mt)
                        mma_tf32(acc[mt][nt], A[mt], b0, b1);
                }
            }
        }
    }

    // epilogue: register accumulators -> gmem
    const int hh = h0 + wm;
    float* pb = out + ((size_t)(b*COUT + oT*128 + wn*32)*64 + hh)*64;
    #pragma unroll
    for (int nt = 0; nt < 4; ++nt){
        float* pn = pb + (size_t)(nt*8 + 2*q)*HW;
        #pragma unroll
        for (int mt = 0; mt < 4; ++mt){
            int w = mt*16 + g;
            pn[w]            = acc[mt][nt][0];
            pn[HW + w]       = acc[mt][nt][1];
            pn[w + 8]        = acc[mt][nt][2];
            pn[HW + w + 8]   = acc[mt][nt][3];
        }
    }
}

// ---------------- K5: BN stats ----------------
__global__ void stats_kernel(const float* __restrict__ out,
                             const float* __restrict__ gamma,
                             const float* __restrict__ beta){
    int c = blockIdx.x;
    float s = 0.f, sq = 0.f;
    for (int b = 0; b < B_; ++b){
        const float* p = out + ((size_t)b*COUT + c)*HW;
        for (int i = threadIdx.x; i < HW; i += 256){
            float vv = p[i]; s += vv; sq += vv*vv;
        }
    }
    __shared__ float r1[8], r2[8];
    for (int o = 16; o; o >>= 1){
        s  += __shfl_down_sync(0xffffffffu, s,  o);
        sq += __shfl_down_sync(0xffffffffu, sq, o);
    }
    if ((threadIdx.x & 31) == 0){ r1[threadIdx.x>>5] = s; r2[threadIdx.x>>5] = sq; }
    __syncthreads();
    if (threadIdx.x < 8){
        s = r1[threadIdx.x]; sq = r2[threadIdx.x];
        for (int o = 4; o; o >>= 1){
            s  += __shfl_down_sync(0x000000ffu, s,  o);
            sq += __shfl_down_sync(0x000000ffu, sq, o);
        }
        if (threadIdx.x == 0){
            const float invN = 1.f/(float)(B_*HW);
            float mean = s * invN;
            float var  = sq * invN - mean*mean;
            float rstd = rsqrtf(var + 1e-5f);
            float sc = rstd * gamma[c];
            g_scale[c] = sc;
            g_shift[c] = beta[c] - mean*sc;
        }
    }
}

// ---------------- K6: normalize ----------------
__global__ void norm_kernel(float* __restrict__ out){
    size_t i = (size_t)blockIdx.x*256 + threadIdx.x;
    int c = (int)((i >> 10) & (COUT-1));
    float sc = g_scale[c], sh = g_shift[c];
    float4* p = (float4*)out;
    float4 vv = p[i];
    vv.x = vv.x*sc + sh; vv.y = vv.y*sc + sh;
    vv.z = vv.z*sc + sh; vv.w = vv.w*sc + sh;
    p[i] = vv;
}

// ---------------- launch ----------------
extern "C" void kernel_launch(void* const* d_in, const int* in_sizes, int n_in,
                              void* d_out, int out_size){
    const float* x     = (const float*)d_in[0];
    const float* wbank = (const float*)d_in[1];
    const float* gamma = (const float*)d_in[2];
    const float* beta  = (const float*)d_in[3];
    const float* w1s = (const float*)d_in[4];
    const float* w2s = (const float*)d_in[5];
    const float* b2s = (const float*)d_in[6];
    const float* w1c = (const float*)d_in[7];
    const float* w2c = (const float*)d_in[8];
    const float* b2c = (const float*)d_in[9];
    const float* w1f = (const float*)d_in[10];
    const float* w2f = (const float*)d_in[11];
    const float* b2f = (const float*)d_in[12];
    const float* w1w = (const float*)d_in[13];
    const float* w2w = (const float*)d_in[14];
    const float* b2w = (const float*)d_in[15];
    float* out = (float*)d_out;

    cudaFuncSetAttribute(conv_kernel, cudaFuncAttributeMaxDynamicSharedMemorySize, CONV_SMEM);

    pool_kernel<<<B_*CIN, 256>>>(x);
    branch_kernel<<<dim3(4, B_), 64>>>(w1s,w2s,b2s, w1c,w2c,b2c, w1f,w2f,b2f, w1w,w2w,b2w);
    alpha_kernel<<<1, 64>>>();
    combine_kernel<<<1024, 256>>>(wbank);
    conv_kernel<<<dim3(2, 32, B_), 256, CONV_SMEM>>>(x, out);
    stats_kernel<<<COUT, 256>>>(out, gamma, beta);
    norm_kernel<<<(int)((size_t)B_*COUT*HW/4/256), 256>>>(out);
}